// round 3
// baseline (speedup 1.0000x reference)
#include <cuda_runtime.h>
#include <cuda_bf16.h>
#include <math.h>

#define Bb 4
#define Ls 2048
#define Es 512
#define Hh 8
#define Dd 64
#define Uu 40
#define NTOP 40
#define BH (Bb*Hh)

// ---------------- scratch (device globals; no allocations allowed) ----------------
__device__ float g_q[Bb*Ls*Es];              // 16 MB, layout [b][l][e], e = h*64+d
__device__ float g_k[Bb*Ls*Es];
__device__ float g_v[Bb*Ls*Es];
__device__ float g_M[BH*Ls];
__device__ int   g_top[BH*NTOP];
__device__ float g_scores[BH*NTOP*Ls];       // 10.5 MB, reused as attn in-place
__device__ float g_upd[BH*NTOP*Dd];
__device__ float g_vmean[BH*Dd];             // [b][h][d] == [b][e]
__device__ float g_base[Bb*Es];

// ---------------- f32x2 packed FMA helpers (full-rate fp32 on sm_103a) ----------------
__device__ __forceinline__ unsigned long long pk2(float lo, float hi) {
    unsigned long long r;
    asm("mov.b64 %0, {%1,%2};" : "=l"(r) : "f"(lo), "f"(hi));
    return r;
}
__device__ __forceinline__ void fma2(unsigned long long& d, unsigned long long a, unsigned long long b) {
    asm("fma.rn.f32x2 %0, %1, %2, %3;" : "=l"(d) : "l"(a), "l"(b), "l"(d));
}
__device__ __forceinline__ float2 upk2(unsigned long long v) {
    float2 f;
    asm("mov.b64 {%0,%1}, %2;" : "=f"(f.x), "=f"(f.y) : "l"(v));
    return f;
}

// ---------------- 1) projections: C = A @ W^T + bias,  A:(8192,512) W:(512,512) ----------------
__global__ void __launch_bounds__(256, 2) proj_gemm(const float* __restrict__ A,
                                                    const float* __restrict__ W,
                                                    const float* __restrict__ bias,
                                                    int which)
{
    float* C = (which == 0) ? g_q : (which == 1) ? g_k : g_v;
    __shared__ float As[16][132];   // [k][m], pad keeps float4 alignment + low conflicts
    __shared__ float Ws[16][132];   // [k][n]
    int m0 = blockIdx.y * 128, n0 = blockIdx.x * 128;
    int tid = threadIdx.x;
    int tx = tid & 15, ty = tid >> 4;

    unsigned long long acc[8][4];
    #pragma unroll
    for (int i = 0; i < 8; i++)
        #pragma unroll
        for (int p = 0; p < 4; p++) acc[i][p] = 0ull;   // bit pattern of {0.f,0.f}

    for (int k0 = 0; k0 < 512; k0 += 16) {
        #pragma unroll
        for (int i = 0; i < 8; i++) {
            int lin = i * 256 + tid;
            int kk = lin & 15, mm = lin >> 4;
            As[kk][mm] = A[(size_t)(m0 + mm) * 512 + k0 + kk];
            Ws[kk][mm] = W[(size_t)(n0 + mm) * 512 + k0 + kk];
        }
        __syncthreads();
        #pragma unroll
        for (int kk = 0; kk < 16; kk++) {
            float4 a0 = *(const float4*)&As[kk][ty * 8];
            float4 a1 = *(const float4*)&As[kk][ty * 8 + 4];
            float4 b0 = *(const float4*)&Ws[kk][tx * 8];
            float4 b1 = *(const float4*)&Ws[kk][tx * 8 + 4];
            unsigned long long bp[4] = { pk2(b0.x, b0.y), pk2(b0.z, b0.w),
                                         pk2(b1.x, b1.y), pk2(b1.z, b1.w) };
            float av[8] = {a0.x, a0.y, a0.z, a0.w, a1.x, a1.y, a1.z, a1.w};
            #pragma unroll
            for (int i = 0; i < 8; i++) {
                unsigned long long ad = pk2(av[i], av[i]);
                #pragma unroll
                for (int p = 0; p < 4; p++) fma2(acc[i][p], ad, bp[p]);
            }
        }
        __syncthreads();
    }
    #pragma unroll
    for (int i = 0; i < 8; i++) {
        int m = m0 + ty * 8 + i;
        int n = n0 + tx * 8;
        float o[8];
        #pragma unroll
        for (int p = 0; p < 4; p++) {
            float2 v = upk2(acc[i][p]);
            o[2*p]   = v.x + bias[n + 2*p];
            o[2*p+1] = v.y + bias[n + 2*p + 1];
        }
        float4* cp = (float4*)&C[(size_t)m * 512 + n];
        cp[0] = make_float4(o[0], o[1], o[2], o[3]);
        cp[1] = make_float4(o[4], o[5], o[6], o[7]);
    }
}

// ---------------- 2) v mean over L per (b,h) ----------------
__global__ void __launch_bounds__(256) vmean_kernel() {
    int bh = blockIdx.x; int b = bh / Hh, h = bh % Hh;
    int d = threadIdx.x & 63, c = threadIdx.x >> 6;
    const float* vb = g_v + (size_t)b * Ls * Es + h * Dd + d;
    float s = 0.f;
    for (int l = c; l < Ls; l += 4) s += vb[(size_t)l * Es];
    __shared__ float sm[256];
    sm[threadIdx.x] = s;
    __syncthreads();
    if (c == 0)
        g_vmean[bh * Dd + d] = (sm[d] + sm[64 + d] + sm[128 + d] + sm[192 + d]) * (1.0f / Ls);
}

__global__ void zero_upd() {
    int i = blockIdx.x * blockDim.x + threadIdx.x;
    if (i < BH * NTOP * Dd) g_upd[i] = 0.f;
}

// ---------------- 3) M[b,h,l] = max_s(q·k_sample) - sum_s(q·k_sample)/L ----------------
// one warp per (b,h,l); lane holds 2 of the 64 q dims; gather loads software-pipelined
__global__ void __launch_bounds__(256) m_kernel(const int* __restrict__ idx) {
    int bh = blockIdx.y; int b = bh / Hh, h = bh % Hh;
    int w = threadIdx.x >> 5, lane = threadIdx.x & 31;
    int l = blockIdx.x * 8 + w;
    const float* qrow = g_q + (size_t)(b * Ls + l) * Es + h * Dd;
    float2 q2 = *(const float2*)(qrow + lane * 2);
    const int* irow = idx + l * Uu;
    int i0 = irow[lane];                                // lanes 0..31 (< U=40)
    int i1 = (lane < 8) ? irow[32 + lane] : 0;
    const float* kbase = g_k + (size_t)b * Ls * Es + h * Dd;
    float mx = -INFINITY, sm = 0.f;
    int j0 = __shfl_sync(0xffffffffu, i0, 0);
    float2 kk = *(const float2*)(kbase + (size_t)j0 * Es + lane * 2);
    #pragma unroll 4
    for (int s = 0; s < Uu; s++) {
        float2 nk = kk;
        if (s + 1 < Uu) {
            int jn = (s + 1 < 32) ? __shfl_sync(0xffffffffu, i0, s + 1)
                                  : __shfl_sync(0xffffffffu, i1, s + 1 - 32);
            nk = *(const float2*)(kbase + (size_t)jn * Es + lane * 2);
        }
        float p = q2.x * kk.x + q2.y * kk.y;
        p += __shfl_xor_sync(0xffffffffu, p, 16);
        p += __shfl_xor_sync(0xffffffffu, p, 8);
        p += __shfl_xor_sync(0xffffffffu, p, 4);
        p += __shfl_xor_sync(0xffffffffu, p, 2);
        p += __shfl_xor_sync(0xffffffffu, p, 1);
        mx = fmaxf(mx, p);
        sm += p;
        kk = nk;
    }
    if (lane == 0) g_M[bh * Ls + l] = mx - sm * (1.0f / Ls);
}

// ---------------- 4) top-40 (set semantics; order irrelevant since scatter uses same set) ----------------
__global__ void __launch_bounds__(256) topk_kernel() {
    int bh = blockIdx.x;
    __shared__ float sv[Ls];
    __shared__ float rv[256];
    __shared__ int ri[256];
    int tid = threadIdx.x;
    for (int i = tid; i < Ls; i += 256) sv[i] = g_M[bh * Ls + i];
    __syncthreads();
    for (int t = 0; t < NTOP; t++) {
        float best = -INFINITY; int bi = Ls;
        for (int i = tid; i < Ls; i += 256) {
            float v = sv[i];
            if (v > best || (v == best && i < bi)) { best = v; bi = i; }
        }
        rv[tid] = best; ri[tid] = bi;
        __syncthreads();
        for (int s = 128; s > 0; s >>= 1) {
            if (tid < s) {
                float ov = rv[tid + s]; int oi = ri[tid + s];
                if (ov > rv[tid] || (ov == rv[tid] && oi < ri[tid])) { rv[tid] = ov; ri[tid] = oi; }
            }
            __syncthreads();
        }
        if (tid == 0) { g_top[bh * NTOP + t] = ri[0]; sv[ri[0]] = -INFINITY; }
        __syncthreads();
    }
}

// ---------------- 5) scores[b,h,u,j] = q[top_u] · k[j]  (no scale, per reference) ----------------
__global__ void __launch_bounds__(256) scores_kernel() {
    int bh = blockIdx.y; int b = bh / Hh, h = bh % Hh;
    int jt = blockIdx.x;                      // 16 tiles of 128 keys
    __shared__ float qs[NTOP][Dd];            // broadcast-only access
    __shared__ float ks[128][65];
    __shared__ int ti[NTOP];
    int tid = threadIdx.x;
    if (tid < NTOP) ti[tid] = g_top[bh * NTOP + tid];
    __syncthreads();
    for (int i = tid; i < NTOP * Dd; i += 256) {
        int u = i >> 6, d = i & 63;
        qs[u][d] = g_q[(size_t)(b * Ls + ti[u]) * Es + h * Dd + d];
    }
    const float* kb = g_k + (size_t)b * Ls * Es + (size_t)jt * 128 * Es + h * Dd;
    for (int i = tid; i < 128 * Dd; i += 256) {
        int j = i >> 6, d = i & 63;
        ks[j][d] = kb[(size_t)j * Es + d];
    }
    __syncthreads();
    int tu = tid >> 5, tj = tid & 31;
    float acc[5][4];
    #pragma unroll
    for (int i = 0; i < 5; i++)
        #pragma unroll
        for (int jj = 0; jj < 4; jj++) acc[i][jj] = 0.f;
    for (int d = 0; d < Dd; d++) {
        float a[5], kv[4];
        #pragma unroll
        for (int i = 0; i < 5; i++) a[i] = qs[tu * 5 + i][d];
        #pragma unroll
        for (int jj = 0; jj < 4; jj++) kv[jj] = ks[tj + 32 * jj][d];
        #pragma unroll
        for (int i = 0; i < 5; i++)
            #pragma unroll
            for (int jj = 0; jj < 4; jj++) acc[i][jj] = fmaf(a[i], kv[jj], acc[i][jj]);
    }
    #pragma unroll
    for (int i = 0; i < 5; i++)
        #pragma unroll
        for (int jj = 0; jj < 4; jj++) {
            int u = tu * 5 + i, j = jt * 128 + tj + 32 * jj;
            g_scores[(size_t)(bh * NTOP + u) * Ls + j] = acc[i][jj];
        }
}

// ---------------- 6) softmax over j, in place ----------------
__global__ void __launch_bounds__(256) softmax_kernel() {
    int row = blockIdx.x;
    float* p = g_scores + (size_t)row * Ls;
    __shared__ float red[256];
    int tid = threadIdx.x;
    float mx = -INFINITY;
    for (int i = tid; i < Ls; i += 256) mx = fmaxf(mx, p[i]);
    red[tid] = mx; __syncthreads();
    for (int s = 128; s; s >>= 1) { if (tid < s) red[tid] = fmaxf(red[tid], red[tid + s]); __syncthreads(); }
    mx = red[0]; __syncthreads();
    float sm = 0.f;
    for (int i = tid; i < Ls; i += 256) sm += __expf(p[i] - mx);
    red[tid] = sm; __syncthreads();
    for (int s = 128; s; s >>= 1) { if (tid < s) red[tid] += red[tid + s]; __syncthreads(); }
    float inv = 1.0f / red[0];
    for (int i = tid; i < Ls; i += 256) p[i] = __expf(p[i] - mx) * inv;
}

// ---------------- 7) upd[u,d] = attn @ v,  split over j-chunks with atomic reduce ----------------
__global__ void __launch_bounds__(256) upd_kernel() {
    int bh = blockIdx.y; int b = bh / Hh, h = bh % Hh;
    int jc = blockIdx.x;                       // 8 chunks of 256 keys
    __shared__ float vs[64][65];
    __shared__ float as[NTOP][64];
    int tid = threadIdx.x;
    int td = tid & 63, tg = tid >> 6;          // td = d, tg*10+i = u
    float acc[10];
    #pragma unroll
    for (int i = 0; i < 10; i++) acc[i] = 0.f;
    for (int jt = 0; jt < 4; jt++) {
        int j0 = jc * 256 + jt * 64;
        const float* vb = g_v + (size_t)b * Ls * Es + (size_t)j0 * Es + h * Dd;
        for (int i = tid; i < 64 * 64; i += 256) { int j = i >> 6, d = i & 63; vs[j][d] = vb[(size_t)j * Es + d]; }
        for (int i = tid; i < NTOP * 64; i += 256) { int u = i >> 6, j = i & 63; as[u][j] = g_scores[(size_t)(bh * NTOP + u) * Ls + j0 + j]; }
        __syncthreads();
        for (int jj = 0; jj < 64; jj++) {
            float vv = vs[jj][td];
            #pragma unroll
            for (int i = 0; i < 10; i++) acc[i] = fmaf(as[tg * 10 + i][jj], vv, acc[i]);
        }
        __syncthreads();
    }
    #pragma unroll
    for (int i = 0; i < 10; i++)
        atomicAdd(&g_upd[((size_t)(bh * NTOP) + tg * 10 + i) * Dd + td], acc[i]);
}

// ---------------- 8) base[b] = concat_h(vmean) @ Wo^T + bo  (one row per batch!) ----------------
__global__ void __launch_bounds__(256) base_kernel(const float* __restrict__ Wo, const float* __restrict__ bo) {
    int b = blockIdx.x;
    __shared__ float cm[Es];
    int tid = threadIdx.x;
    cm[tid] = g_vmean[b * Es + tid];
    cm[tid + 256] = g_vmean[b * Es + 256 + tid];
    __syncthreads();
    for (int r = 0; r < 2; r++) {
        int e = r * 256 + tid;
        const float4* wr = (const float4*)(Wo + (size_t)e * Es);
        float acc = bo[e];
        for (int c4 = 0; c4 < Es / 4; c4++) {
            float4 w = wr[c4];
            acc += cm[4*c4] * w.x + cm[4*c4+1] * w.y + cm[4*c4+2] * w.z + cm[4*c4+3] * w.w;
        }
        g_base[b * Es + e] = acc;
    }
}

// ---------------- 9) out = broadcast(base) ----------------
__global__ void broadcast_kernel(float4* __restrict__ out) {
    int idx = blockIdx.x * blockDim.x + threadIdx.x;   // B*L*E/4 float4s
    if (idx < Bb * Ls * Es / 4) {
        int per_b = Ls * Es / 4;
        int b = idx / per_b;
        int e4 = idx & (Es / 4 - 1);
        out[idx] = ((const float4*)g_base)[b * (Es / 4) + e4];
    }
}

// ---------------- 10) corrections: out[b, top_l] += (upd - vmean)_h @ Wo[:, h-slice]^T ----------------
__global__ void __launch_bounds__(128) corr_kernel(const float* __restrict__ Wo, float* __restrict__ out) {
    int g = blockIdx.x;                        // BH*NTOP
    int bh = g / NTOP;
    int b = bh / Hh, h = bh % Hh;
    int l = g_top[g];
    __shared__ float delta[Dd];
    int tid = threadIdx.x;
    if (tid < Dd) delta[tid] = g_upd[(size_t)g * Dd + tid] - g_vmean[bh * Dd + tid];
    __syncthreads();
    float* orow = out + (size_t)(b * Ls + l) * Es;
    for (int r = 0; r < 4; r++) {
        int e = r * 128 + tid;
        const float4* wr = (const float4*)(Wo + (size_t)e * Es + h * Dd);
        float acc = 0.f;
        #pragma unroll
        for (int q = 0; q < 16; q++) {
            float4 w = wr[q];
            acc += delta[4*q] * w.x + delta[4*q+1] * w.y + delta[4*q+2] * w.z + delta[4*q+3] * w.w;
        }
        atomicAdd(orow + e, acc);
    }
}

// ---------------- launch ----------------
extern "C" void kernel_launch(void* const* d_in, const int* in_sizes, int n_in,
                              void* d_out, int out_size) {
    const float* query = (const float*)d_in[0];
    const float* key   = (const float*)d_in[1];
    const float* value = (const float*)d_in[2];
    const int*   idx   = (const int*)d_in[3];
    const float* Wq = (const float*)d_in[4];  const float* bq = (const float*)d_in[5];
    const float* Wk = (const float*)d_in[6];  const float* bk = (const float*)d_in[7];
    const float* Wv = (const float*)d_in[8];  const float* bv = (const float*)d_in[9];
    const float* Wo = (const float*)d_in[10]; const float* bo = (const float*)d_in[11];
    float* out = (float*)d_out;

    dim3 gproj(Es / 128, (Bb * Ls) / 128);     // (4, 64)
    proj_gemm<<<gproj, 256>>>(query, Wq, bq, 0);
    proj_gemm<<<gproj, 256>>>(key,   Wk, bk, 1);
    proj_gemm<<<gproj, 256>>>(value, Wv, bv, 2);

    vmean_kernel<<<BH, 256>>>();
    zero_upd<<<(BH * NTOP * Dd + 255) / 256, 256>>>();

    m_kernel<<<dim3(Ls / 8, BH), 256>>>(idx);
    topk_kernel<<<BH, 256>>>();

    scores_kernel<<<dim3(16, BH), 256>>>();
    softmax_kernel<<<BH * NTOP, 256>>>();
    upd_kernel<<<dim3(8, BH), 256>>>();

    base_kernel<<<Bb, 256>>>(Wo, bo);
    broadcast_kernel<<<(Bb * Ls * Es / 4 + 255) / 256, 256>>>((float4*)out);
    corr_kernel<<<BH * NTOP, 128>>>(Wo, out);
}

// round 6
// speedup vs baseline: 1.6541x; 1.6541x over previous
#include <cuda_runtime.h>
#include <cuda_bf16.h>
#include <math.h>
#include <stdint.h>

#define Bb 4
#define Ls 2048
#define Es 512
#define Hh 8
#define Dd 64
#define Uu 40
#define NTOP 40
#define BH (Bb*Hh)

// ---------------- scratch (device globals; no allocations allowed) ----------------
__device__ float g_q[Bb*Ls*Es];              // fp32 projected q [b][l][e], e=h*64+d
__device__ float g_k[Bb*Ls*Es];
__device__ float g_v[Bb*Ls*Es];
__device__ __nv_bfloat16 g_abf[3*Bb*Ls*1024];  // [proj][row][0:512]=hi,[512:1024]=lo
__device__ __nv_bfloat16 g_wbf[3*Es*1024];     // [proj][n][0:512]=hi,[512:1024]=lo
__device__ float g_M[BH*Ls];
__device__ int   g_top[BH*NTOP];
__device__ float g_scores[BH*NTOP*Ls];
__device__ float g_upd[BH*NTOP*Dd];
__device__ float g_vmean[BH*Dd];
__device__ float g_base[Bb*Es];

// ================= helpers =================
__device__ __forceinline__ uint32_t smem_u32(const void* p) {
    uint32_t a;
    asm("{ .reg .u64 t; cvta.to.shared.u64 t, %1; cvt.u32.u64 %0, t; }" : "=r"(a) : "l"(p));
    return a;
}

__device__ __forceinline__ void cpa16(uint32_t s, const void* g) {
    asm volatile("cp.async.cg.shared.global [%0], [%1], 16;" :: "r"(s), "l"(g));
}
#define CPA_COMMIT() asm volatile("cp.async.commit_group;" ::: "memory")
#define CPA_WAIT(n)  asm volatile("cp.async.wait_group %0;" :: "n"(n) : "memory")

#define LDSM_X4(r, addr) \
    asm volatile("ldmatrix.sync.aligned.m8n8.x4.shared.b16 {%0,%1,%2,%3}, [%4];" \
        : "=r"((r)[0]), "=r"((r)[1]), "=r"((r)[2]), "=r"((r)[3]) : "r"(addr))
#define LDSM_X2(r, addr) \
    asm volatile("ldmatrix.sync.aligned.m8n8.x2.shared.b16 {%0,%1}, [%2];" \
        : "=r"((r)[0]), "=r"((r)[1]) : "r"(addr))

__device__ __forceinline__ void mma16816(float* d, const uint32_t* a, const uint32_t* b) {
    asm volatile(
        "mma.sync.aligned.m16n8k16.row.col.f32.bf16.bf16.f32 "
        "{%0,%1,%2,%3}, {%4,%5,%6,%7}, {%8,%9}, {%0,%1,%2,%3};"
        : "+f"(d[0]), "+f"(d[1]), "+f"(d[2]), "+f"(d[3])
        : "r"(a[0]), "r"(a[1]), "r"(a[2]), "r"(a[3]), "r"(b[0]), "r"(b[1]));
}

// ================= 0) split-bf16 conversion =================
__device__ __forceinline__ void split4(float4 x, __nv_bfloat16* hi, __nv_bfloat16* lo) {
    float xs[4] = {x.x, x.y, x.z, x.w};
    #pragma unroll
    for (int i = 0; i < 4; i++) {
        __nv_bfloat16 h = __float2bfloat16_rn(xs[i]);
        hi[i] = h;
        lo[i] = __float2bfloat16_rn(xs[i] - __bfloat162float(h));
    }
}

__global__ void __launch_bounds__(256) cvt_inputs(const float* __restrict__ q,
                                                  const float* __restrict__ k,
                                                  const float* __restrict__ v) {
    int p = blockIdx.z;
    const float* s = (p == 0) ? q : (p == 1) ? k : v;
    __nv_bfloat16* dst = g_abf + (size_t)p * Bb * Ls * 1024;
    int i = blockIdx.x * 256 + threadIdx.x;           // over 8192*512/4
    float4 x = ((const float4*)s)[i];
    int row = i >> 7, c4 = i & 127;
    __nv_bfloat16 hi[4], lo[4];
    split4(x, hi, lo);
    *(uint2*)&dst[(size_t)row * 1024 + c4 * 4]       = *(uint2*)hi;
    *(uint2*)&dst[(size_t)row * 1024 + 512 + c4 * 4] = *(uint2*)lo;
}

__global__ void __launch_bounds__(256) cvt_weights(const float* __restrict__ wq,
                                                   const float* __restrict__ wk,
                                                   const float* __restrict__ wv) {
    int p = blockIdx.z;
    const float* s = (p == 0) ? wq : (p == 1) ? wk : wv;
    __nv_bfloat16* dst = g_wbf + (size_t)p * Es * 1024;
    int i = blockIdx.x * 256 + threadIdx.x;           // over 512*512/4
    float4 x = ((const float4*)s)[i];
    int row = i >> 7, c4 = i & 127;
    __nv_bfloat16 hi[4], lo[4];
    split4(x, hi, lo);
    *(uint2*)&dst[(size_t)row * 1024 + c4 * 4]       = *(uint2*)hi;
    *(uint2*)&dst[(size_t)row * 1024 + 512 + c4 * 4] = *(uint2*)lo;
}

// ================= 1) mma.sync projection GEMM =================
// C[8192,512] = A'[8192,1536] @ B'[512,1536]^T per proj (split-bf16 3-term:
// AhBh + AhBl + AlBh). CTA tile 128x128, K-chunk 64, double-buffered cp.async.
#define NCHUNK 24
#define CH_BYTES 16384          // 128 rows * 64 bf16 * 2B
#define SM_TOT (4*CH_BYTES)     // A0,B0,A1,B1

__device__ __forceinline__ void chunk_offs(int c, int& ak, int& bk) {
    int r = c & 7, s = c >> 3;
    ak = ((s == 2) ? 512 : 0) + r * 64;
    bk = ((s == 1) ? 512 : 0) + r * 64;
}

// swizzled smem byte offset: 128x64 bf16 tile, 128B rows, XOR-by-row swizzle
__device__ __forceinline__ uint32_t tswz(int row, int c16) {
    return (uint32_t)(row * 128 + c16 * 16) ^ (uint32_t)((row & 7) << 4);
}

__global__ void __launch_bounds__(256, 2) proj_mma(const float* __restrict__ bq,
                                                   const float* __restrict__ bk_,
                                                   const float* __restrict__ bv) {
    extern __shared__ char smem[];
    int z = blockIdx.z;
    int m0 = blockIdx.y * 128, n0 = blockIdx.x * 128;
    const __nv_bfloat16* Ab = g_abf + (size_t)z * Bb * Ls * 1024;
    const __nv_bfloat16* Wb = g_wbf + (size_t)z * Es * 1024;
    const float* bias = (z == 0) ? bq : (z == 1) ? bk_ : bv;
    float* C = (z == 0) ? g_q : (z == 1) ? g_k : g_v;

    uint32_t sb = smem_u32(smem);
    int tid = threadIdx.x, wid = tid >> 5, lane = tid & 31;
    uint32_t abuf[2] = { sb,                sb + 2 * CH_BYTES };
    uint32_t bbuf[2] = { sb + CH_BYTES,     sb + 3 * CH_BYTES };

    int wm = (wid & 1) * 64;        // warp m offset within CTA tile
    int wn = (wid >> 1) * 32;       // warp n offset

    float acc[4][4][4];
    #pragma unroll
    for (int mi = 0; mi < 4; mi++)
        #pragma unroll
        for (int ni = 0; ni < 4; ni++)
            #pragma unroll
            for (int e = 0; e < 4; e++) acc[mi][ni][e] = 0.f;

    auto load_chunk = [&](int c, int p) {
        int ak, bk; chunk_offs(c, ak, bk);
        #pragma unroll
        for (int i = 0; i < 4; i++) {
            int j = tid + i * 256; int row = j >> 3, c16 = j & 7;
            cpa16(abuf[p] + tswz(row, c16), Ab + (size_t)(m0 + row) * 1024 + ak + c16 * 8);
        }
        #pragma unroll
        for (int i = 0; i < 4; i++) {
            int j = tid + i * 256; int row = j >> 3, c16 = j & 7;
            cpa16(bbuf[p] + tswz(row, c16), Wb + (size_t)(n0 + row) * 1024 + bk + c16 * 8);
        }
        CPA_COMMIT();
    };

    load_chunk(0, 0);
    load_chunk(1, 1);

    int lrow = lane & 15, lsel = lane >> 4;          // ldmatrix.x4 addressing (A)
    int brow = lane & 7,  bsel = (lane >> 3) & 1;    // ldmatrix.x2 addressing (B)

    for (int c = 0; c < NCHUNK; c++) {
        int p = c & 1;
        if (c + 1 < NCHUNK) { CPA_WAIT(1); } else { CPA_WAIT(0); }
        __syncthreads();
        #pragma unroll
        for (int ks = 0; ks < 4; ks++) {
            uint32_t af[4][4], bf[4][2];
            #pragma unroll
            for (int mi = 0; mi < 4; mi++) {
                uint32_t ad = abuf[p] + tswz(wm + mi * 16 + lrow, ks * 2 + lsel);
                LDSM_X4(af[mi], ad);
            }
            #pragma unroll
            for (int ni = 0; ni < 4; ni++) {
                uint32_t bd = bbuf[p] + tswz(wn + ni * 8 + brow, ks * 2 + bsel);
                LDSM_X2(bf[ni], bd);
            }
            #pragma unroll
            for (int mi = 0; mi < 4; mi++)
                #pragma unroll
                for (int ni = 0; ni < 4; ni++)
                    mma16816(acc[mi][ni], af[mi], bf[ni]);
        }
        __syncthreads();
        if (c + 2 < NCHUNK) load_chunk(c + 2, p);
    }

    // epilogue: regs -> global, add bias
    int r0 = lane >> 2, cp2 = (lane & 3) * 2;
    #pragma unroll
    for (int ni = 0; ni < 4; ni++) {
        int col = n0 + wn + ni * 8 + cp2;
        float2 bv2 = *(const float2*)&bias[col];
        #pragma unroll
        for (int mi = 0; mi < 4; mi++) {
            int row = m0 + wm + mi * 16 + r0;
            float2 v0 = { acc[mi][ni][0] + bv2.x, acc[mi][ni][1] + bv2.y };
            float2 v1 = { acc[mi][ni][2] + bv2.x, acc[mi][ni][3] + bv2.y };
            *(float2*)&C[(size_t)row * 512 + col] = v0;
            *(float2*)&C[(size_t)(row + 8) * 512 + col] = v1;
        }
    }
}

// ================= 2) zero scratch + vmean (split-L, atomic) =================
__global__ void zero_scratch() {
    int i = blockIdx.x * blockDim.x + threadIdx.x;
    if (i < BH * NTOP * Dd) g_upd[i] = 0.f;
    if (i < BH * Dd) g_vmean[i] = 0.f;
}

__global__ void __launch_bounds__(256) vmean_kernel() {
    int bh = blockIdx.x; int b = bh / Hh, h = bh % Hh;
    int chunk = blockIdx.y;                              // 8 chunks of 256 l
    int d = threadIdx.x & 63, c = threadIdx.x >> 6;
    const float* vb = g_v + (size_t)b * Ls * Es + (size_t)chunk * 256 * Es + h * Dd + d;
    float s = 0.f;
    for (int l = c; l < 256; l += 4) s += vb[(size_t)l * Es];
    __shared__ float sm[256];
    sm[threadIdx.x] = s;
    __syncthreads();
    if (c == 0)
        atomicAdd(&g_vmean[bh * Dd + d],
                  (sm[d] + sm[64 + d] + sm[128 + d] + sm[192 + d]) * (1.0f / Ls));
}

// ================= 3) M scoring: warp per (b,h,l), 8 lanes per sample =================
__global__ void __launch_bounds__(256) m_kernel(const int* __restrict__ idx) {
    int bh = blockIdx.y; int b = bh >> 3, h = bh & 7;
    int w = threadIdx.x >> 5, lane = threadIdx.x & 31;
    int l = blockIdx.x * 8 + w;
    int sg = lane >> 3, dg = lane & 7;
    const float* qrow = g_q + (size_t)(b * Ls + l) * Es + h * Dd + dg * 8;
    float4 q0 = *(const float4*)qrow;
    float4 q1 = *(const float4*)(qrow + 4);
    const int* irow = idx + l * Uu;
    const float* kb = g_k + (size_t)b * Ls * Es + h * Dd + dg * 8;
    float mx = -INFINITY, sm = 0.f;
    #pragma unroll
    for (int s0 = 0; s0 < Uu; s0 += 4) {
        int row = irow[s0 + sg];
        const float* kr = kb + (size_t)row * Es;
        float4 k0 = *(const float4*)kr;
        float4 k1 = *(const float4*)(kr + 4);
        float p = q0.x * k0.x + q0.y * k0.y + q0.z * k0.z + q0.w * k0.w
                + q1.x * k1.x + q1.y * k1.y + q1.z * k1.z + q1.w * k1.w;
        p += __shfl_down_sync(0xffffffffu, p, 4);
        p += __shfl_down_sync(0xffffffffu, p, 2);
        p += __shfl_down_sync(0xffffffffu, p, 1);
        if (dg == 0) { mx = fmaxf(mx, p); sm += p; }
    }
    mx = fmaxf(mx, __shfl_xor_sync(0xffffffffu, mx, 8));
    mx = fmaxf(mx, __shfl_xor_sync(0xffffffffu, mx, 16));
    sm += __shfl_xor_sync(0xffffffffu, sm, 8);
    sm += __shfl_xor_sync(0xffffffffu, sm, 16);
    if (lane == 0) g_M[bh * Ls + l] = mx - sm * (1.0f / Ls);
}

// ================= 4) top-40 =================
__global__ void __launch_bounds__(256) topk_kernel() {
    int bh = blockIdx.x;
    __shared__ float sv[Ls];
    __shared__ float rv[256];
    __shared__ int ri[256];
    int tid = threadIdx.x;
    for (int i = tid; i < Ls; i += 256) sv[i] = g_M[bh * Ls + i];
    __syncthreads();
    for (int t = 0; t < NTOP; t++) {
        float best = -INFINITY; int bi = Ls;
        for (int i = tid; i < Ls; i += 256) {
            float v = sv[i];
            if (v > best || (v == best && i < bi)) { best = v; bi = i; }
        }
        rv[tid] = best; ri[tid] = bi;
        __syncthreads();
        for (int s = 128; s > 0; s >>= 1) {
            if (tid < s) {
                float ov = rv[tid + s]; int oi = ri[tid + s];
                if (ov > rv[tid] || (ov == rv[tid] && oi < ri[tid])) { rv[tid] = ov; ri[tid] = oi; }
            }
            __syncthreads();
        }
        if (tid == 0) { g_top[bh * NTOP + t] = ri[0]; sv[ri[0]] = -INFINITY; }
        __syncthreads();
    }
}

// ================= 5) scores =================
__global__ void __launch_bounds__(256) scores_kernel() {
    int bh = blockIdx.y; int b = bh / Hh, h = bh % Hh;
    int jt = blockIdx.x;
    __shared__ float qs[NTOP][Dd];
    __shared__ float ks[128][65];
    __shared__ int ti[NTOP];
    int tid = threadIdx.x;
    if (tid < NTOP) ti[tid] = g_top[bh * NTOP + tid];
    __syncthreads();
    for (int i = tid; i < NTOP * Dd; i += 256) {
        int u = i >> 6, d = i & 63;
        qs[u][d] = g_q[(size_t)(b * Ls + ti[u]) * Es + h * Dd + d];
    }
    const float* kb = g_k + (size_t)b * Ls * Es + (size_t)jt * 128 * Es + h * Dd;
    for (int i = tid; i < 128 * Dd; i += 256) {
        int j = i >> 6, d = i & 63;
        ks[j][d] = kb[(size_t)j * Es + d];
    }
    __syncthreads();
    int tu = tid >> 5, tj = tid & 31;
    float acc[5][4];
    #pragma unroll
    for (int i = 0; i < 5; i++)
        #pragma unroll
        for (int jj = 0; jj < 4; jj++) acc[i][jj] = 0.f;
    for (int d = 0; d < Dd; d++) {
        float a[5], kv[4];
        #pragma unroll
        for (int i = 0; i < 5; i++) a[i] = qs[tu * 5 + i][d];
        #pragma unroll
        for (int jj = 0; jj < 4; jj++) kv[jj] = ks[tj + 32 * jj][d];
        #pragma unroll
        for (int i = 0; i < 5; i++)
            #pragma unroll
            for (int jj = 0; jj < 4; jj++) acc[i][jj] = fmaf(a[i], kv[jj], acc[i][jj]);
    }
    #pragma unroll
    for (int i = 0; i < 5; i++)
        #pragma unroll
        for (int jj = 0; jj < 4; jj++) {
            int u = tu * 5 + i, j = jt * 128 + tj + 32 * jj;
            g_scores[(size_t)(bh * NTOP + u) * Ls + j] = acc[i][jj];
        }
}

// ================= 6) softmax =================
__global__ void __launch_bounds__(256) softmax_kernel() {
    int row = blockIdx.x;
    float* p = g_scores + (size_t)row * Ls;
    __shared__ float red[256];
    int tid = threadIdx.x;
    float mx = -INFINITY;
    for (int i = tid; i < Ls; i += 256) mx = fmaxf(mx, p[i]);
    red[tid] = mx; __syncthreads();
    for (int s = 128; s; s >>= 1) { if (tid < s) red[tid] = fmaxf(red[tid], red[tid + s]); __syncthreads(); }
    mx = red[0]; __syncthreads();
    float sm = 0.f;
    for (int i = tid; i < Ls; i += 256) sm += __expf(p[i] - mx);
    red[tid] = sm; __syncthreads();
    for (int s = 128; s; s >>= 1) { if (tid < s) red[tid] += red[tid + s]; __syncthreads(); }
    float inv = 1.0f / red[0];
    for (int i = tid; i < Ls; i += 256) p[i] = __expf(p[i] - mx) * inv;
}

// ================= 7) upd = attn @ v =================
__global__ void __launch_bounds__(256) upd_kernel() {
    int bh = blockIdx.y; int b = bh / Hh, h = bh % Hh;
    int jc = blockIdx.x;
    __shared__ float vs[64][65];
    __shared__ float as[NTOP][64];
    int tid = threadIdx.x;
    int td = tid & 63, tg = tid >> 6;
    float acc[10];
    #pragma unroll
    for (int i = 0; i < 10; i++) acc[i] = 0.f;
    for (int jt = 0; jt < 4; jt++) {
        int j0 = jc * 256 + jt * 64;
        const float* vb = g_v + (size_t)b * Ls * Es + (size_t)j0 * Es + h * Dd;
        for (int i = tid; i < 64 * 64; i += 256) { int j = i >> 6, d = i & 63; vs[j][d] = vb[(size_t)j * Es + d]; }
        for (int i = tid; i < NTOP * 64; i += 256) { int u = i >> 6, j = i & 63; as[u][j] = g_scores[(size_t)(bh * NTOP + u) * Ls + j0 + j]; }
        __syncthreads();
        for (int jj = 0; jj < 64; jj++) {
            float vv = vs[jj][td];
            #pragma unroll
            for (int i = 0; i < 10; i++) acc[i] = fmaf(as[tg * 10 + i][jj], vv, acc[i]);
        }
        __syncthreads();
    }
    #pragma unroll
    for (int i = 0; i < 10; i++)
        atomicAdd(&g_upd[((size_t)(bh * NTOP) + tg * 10 + i) * Dd + td], acc[i]);
}

// ================= 8-10) base / broadcast / corrections =================
__global__ void __launch_bounds__(256) base_kernel(const float* __restrict__ Wo, const float* __restrict__ bo) {
    int b = blockIdx.x;
    __shared__ float cm[Es];
    int tid = threadIdx.x;
    cm[tid] = g_vmean[b * Es + tid];
    cm[tid + 256] = g_vmean[b * Es + 256 + tid];
    __syncthreads();
    for (int r = 0; r < 2; r++) {
        int e = r * 256 + tid;
        const float4* wr = (const float4*)(Wo + (size_t)e * Es);
        float acc = bo[e];
        for (int c4 = 0; c4 < Es / 4; c4++) {
            float4 w = wr[c4];
            acc += cm[4*c4] * w.x + cm[4*c4+1] * w.y + cm[4*c4+2] * w.z + cm[4*c4+3] * w.w;
        }
        g_base[b * Es + e] = acc;
    }
}

__global__ void broadcast_kernel(float4* __restrict__ out) {
    int idx = blockIdx.x * blockDim.x + threadIdx.x;
    if (idx < Bb * Ls * Es / 4) {
        int per_b = Ls * Es / 4;
        int b = idx / per_b;
        int e4 = idx & (Es / 4 - 1);
        out[idx] = ((const float4*)g_base)[b * (Es / 4) + e4];
    }
}

__global__ void __launch_bounds__(128) corr_kernel(const float* __restrict__ Wo, float* __restrict__ out) {
    int g = blockIdx.x;
    int bh = g / NTOP;
    int b = bh / Hh, h = bh % Hh;
    int l = g_top[g];
    __shared__ float delta[Dd];
    int tid = threadIdx.x;
    if (tid < Dd) delta[tid] = g_upd[(size_t)g * Dd + tid] - g_vmean[bh * Dd + tid];
    __syncthreads();
    float* orow = out + (size_t)(b * Ls + l) * Es;
    for (int r = 0; r < 4; r++) {
        int e = r * 128 + tid;
        const float4* wr = (const float4*)(Wo + (size_t)e * Es + h * Dd);
        float acc = 0.f;
        #pragma unroll
        for (int q = 0; q < 16; q++) {
            float4 w = wr[q];
            acc += delta[4*q] * w.x + delta[4*q+1] * w.y + delta[4*q+2] * w.z + delta[4*q+3] * w.w;
        }
        atomicAdd(orow + e, acc);
    }
}

// ================= launch =================
extern "C" void kernel_launch(void* const* d_in, const int* in_sizes, int n_in,
                              void* d_out, int out_size) {
    const float* query = (const float*)d_in[0];
    const float* key   = (const float*)d_in[1];
    const float* value = (const float*)d_in[2];
    const int*   idx   = (const int*)d_in[3];
    const float* Wq = (const float*)d_in[4];  const float* bq = (const float*)d_in[5];
    const float* Wk = (const float*)d_in[6];  const float* bk = (const float*)d_in[7];
    const float* Wv = (const float*)d_in[8];  const float* bv = (const float*)d_in[9];
    const float* Wo = (const float*)d_in[10]; const float* bo = (const float*)d_in[11];
    float* out = (float*)d_out;

    cvt_inputs<<<dim3(4096, 1, 3), 256>>>(query, key, value);
    cvt_weights<<<dim3(256, 1, 3), 256>>>(Wq, Wk, Wv);

    cudaFuncSetAttribute(proj_mma, cudaFuncAttributeMaxDynamicSharedMemorySize, SM_TOT);
    proj_mma<<<dim3(4, 64, 3), 256, SM_TOT>>>(bq, bk, bv);

    zero_scratch<<<(BH * NTOP * Dd + 255) / 256, 256>>>();
    vmean_kernel<<<dim3(BH, 8), 256>>>();

    m_kernel<<<dim3(Ls / 8, BH), 256>>>(idx);
    topk_kernel<<<BH, 256>>>();

    scores_kernel<<<dim3(16, BH), 256>>>();
    softmax_kernel<<<BH * NTOP, 256>>>();
    upd_kernel<<<dim3(8, BH), 256>>>();

    base_kernel<<<Bb, 256>>>(Wo, bo);
    broadcast_kernel<<<(Bb * Ls * Es / 4 + 255) / 256, 256>>>((float4*)out);
    corr_kernel<<<BH * NTOP, 128>>>(Wo, out);
}